// round 5
// baseline (speedup 1.0000x reference)
#include <cuda_runtime.h>
#include <cuda_bf16.h>
#include <cstdint>

#define LN_EPS 1e-5f

static constexpr int Fdim = 64;
static constexpr int Hdim = 128;

// cross-CTA combine scratch (written every launch before read; counter self-resets)
__device__ int d_partial[2048][128];
__device__ int d_counter[1024];

__device__ __forceinline__ float bf16_round(float x) {
    return __bfloat162float(__float2bfloat16_rn(x));
}
// pack two floats as bf16x2: lo -> low half, hi -> high half
__device__ __forceinline__ uint32_t packbf(float lo, float hi) {
    uint32_t r;
    asm("cvt.rn.bf16x2.f32 %0, %1, %2;" : "=r"(r) : "f"(hi), "f"(lo));
    return r;
}
// residual pair vs the bf16x2 already packed in 'h'
__device__ __forceinline__ uint32_t resid(uint32_t h, float lo, float hi) {
    float hlo = __uint_as_float(h << 16);
    float hhi = __uint_as_float(h & 0xffff0000u);
    return packbf(lo - hlo, hi - hhi);
}

__device__ __forceinline__ void mma_bf16(float c[4], const uint32_t a[4], const uint32_t b[2]) {
    asm volatile(
        "mma.sync.aligned.m16n8k16.row.col.f32.bf16.bf16.f32 "
        "{%0,%1,%2,%3}, {%4,%5,%6,%7}, {%8,%9}, {%0,%1,%2,%3};\n"
        : "+f"(c[0]), "+f"(c[1]), "+f"(c[2]), "+f"(c[3])
        : "r"(a[0]), "r"(a[1]), "r"(a[2]), "r"(a[3]), "r"(b[0]), "r"(b[1]));
}

// grid = 2N: CTA (n, half) owns L/2 rows (16 warps x 16 rows, single sweep).
// bf16x3-split GEMM -> bias -> LN -> ReLU -> y (streaming stores); pooled max:
// smem atomics -> global partial -> last-arriver combines, writes g, broadcasts.
extern "C" __global__ void __launch_bounds__(512, 1)
fused_kernel(const float* __restrict__ x, const int* __restrict__ mask,
             const float* __restrict__ W, const float* __restrict__ bias,
             const float* __restrict__ gamma, const float* __restrict__ beta,
             float* __restrict__ out, float* __restrict__ gout, int L)
{
    __shared__ uint4 Bfrag[4 * 16 * 32];   // 32 KB
    __shared__ int   gsm[128];
    __shared__ int   sIsLast;

    const int tid  = threadIdx.x;
    const int bidx = blockIdx.x;
    const int n    = bidx >> 1;
    const int half = bidx & 1;
    const int Lh   = L >> 1;
    const int rb0  = half * Lh;

    // pack W into bf16 mma B-fragment order (hi + residual lo)
    for (int idx = tid; idx < 4 * 16 * 32; idx += 512) {
        int lane = idx & 31;
        int t    = (idx >> 5) & 15;
        int ks   = idx >> 9;
        int q = lane >> 2, s = lane & 3;
        int h  = t * 8 + q;
        int f0 = ks * 16 + s * 2;
        float2 w01 = *reinterpret_cast<const float2*>(W + h * Fdim + f0);
        float2 w89 = *reinterpret_cast<const float2*>(W + h * Fdim + f0 + 8);
        uint4 v;
        v.x = packbf(w01.x, w01.y);
        v.y = packbf(w89.x, w89.y);
        v.z = packbf(w01.x - bf16_round(w01.x), w01.y - bf16_round(w01.y));
        v.w = packbf(w89.x - bf16_round(w89.x), w89.y - bf16_round(w89.y));
        Bfrag[idx] = v;
    }
    if (tid < 128) gsm[tid] = 0;
    __syncthreads();

    const int lane = tid & 31;
    const int warp = tid >> 5;
    const int q = lane >> 2, s = lane & 3;

    {   // ---- single sweep: 16 rows per warp ----
        const int rb = rb0 + warp * 16;
        const size_t rowA = (size_t)n * L + rb + q;
        const size_t rowB = rowA + 8;
        const float* xA = x + rowA * Fdim;
        const float* xB = x + rowB * Fdim;

        float acc[16][4];
        #pragma unroll
        for (int t = 0; t < 16; t++)
            acc[t][0] = acc[t][1] = acc[t][2] = acc[t][3] = 0.f;

        #pragma unroll
        for (int ks = 0; ks < 4; ks++) {
            const int f0 = ks * 16 + s * 2;
            float2 A0 = __ldcs(reinterpret_cast<const float2*>(xA + f0));
            float2 A8 = __ldcs(reinterpret_cast<const float2*>(xA + f0 + 8));
            float2 B0 = __ldcs(reinterpret_cast<const float2*>(xB + f0));
            float2 B8 = __ldcs(reinterpret_cast<const float2*>(xB + f0 + 8));
            uint32_t ah[4] = { packbf(A0.x, A0.y), packbf(B0.x, B0.y),
                               packbf(A8.x, A8.y), packbf(B8.x, B8.y) };
            uint32_t al[4] = { resid(ah[0], A0.x, A0.y), resid(ah[1], B0.x, B0.y),
                               resid(ah[2], A8.x, A8.y), resid(ah[3], B8.x, B8.y) };
            const uint4* Bp = Bfrag + ks * 512 + lane;
            #pragma unroll
            for (int t = 0; t < 16; t++) {
                uint4 bv = Bp[t * 32];
                uint32_t bh[2] = { bv.x, bv.y };
                uint32_t bl[2] = { bv.z, bv.w };
                mma_bf16(acc[t], ah, bh);   // hi*hi
                mma_bf16(acc[t], al, bh);   // lo*hi
                mma_bf16(acc[t], ah, bl);   // hi*lo
            }
        }

        #pragma unroll
        for (int t = 0; t < 16; t++) {
            float2 bb = *reinterpret_cast<const float2*>(bias + t * 8 + 2 * s);
            acc[t][0] += bb.x; acc[t][1] += bb.y;
            acc[t][2] += bb.x; acc[t][3] += bb.y;
        }

        float sumA = 0.f, sqA = 0.f, sumB = 0.f, sqB = 0.f;
        #pragma unroll
        for (int t = 0; t < 16; t++) {
            sumA += acc[t][0] + acc[t][1];
            sqA  += acc[t][0] * acc[t][0] + acc[t][1] * acc[t][1];
            sumB += acc[t][2] + acc[t][3];
            sqB  += acc[t][2] * acc[t][2] + acc[t][3] * acc[t][3];
        }
        #pragma unroll
        for (int m = 1; m <= 2; m <<= 1) {
            sumA += __shfl_xor_sync(0xffffffffu, sumA, m);
            sqA  += __shfl_xor_sync(0xffffffffu, sqA, m);
            sumB += __shfl_xor_sync(0xffffffffu, sumB, m);
            sqB  += __shfl_xor_sync(0xffffffffu, sqB, m);
        }
        const float inv = 1.0f / (float)Hdim;
        float muA = sumA * inv, muB = sumB * inv;
        float rsA = rsqrtf(fmaxf(sqA * inv - muA * muA, 0.f) + LN_EPS);
        float rsB = rsqrtf(fmaxf(sqB * inv - muB * muB, 0.f) + LN_EPS);

        const bool mA = (mask[rowA] != 0);
        const bool mB = (mask[rowB] != 0);
        float* outA = out + rowA * (2 * Hdim);
        float* outB = out + rowB * (2 * Hdim);

        float p0[16], p1[16];
        #pragma unroll
        for (int t = 0; t < 16; t++) {
            int col = t * 8 + 2 * s;
            float2 gg = *reinterpret_cast<const float2*>(gamma + col);
            float2 bt = *reinterpret_cast<const float2*>(beta + col);
            float yA0 = fmaxf((acc[t][0] - muA) * rsA * gg.x + bt.x, 0.f);
            float yA1 = fmaxf((acc[t][1] - muA) * rsA * gg.y + bt.y, 0.f);
            float yB0 = fmaxf((acc[t][2] - muB) * rsB * gg.x + bt.x, 0.f);
            float yB1 = fmaxf((acc[t][3] - muB) * rsB * gg.y + bt.y, 0.f);
            __stcs(reinterpret_cast<float2*>(outA + col), make_float2(yA0, yA1));
            __stcs(reinterpret_cast<float2*>(outB + col), make_float2(yB0, yB1));
            p0[t] = fmaxf(mA ? yA0 : 0.f, mB ? yB0 : 0.f);
            p1[t] = fmaxf(mA ? yA1 : 0.f, mB ? yB1 : 0.f);
        }

        #pragma unroll
        for (int t = 0; t < 16; t++) {
            #pragma unroll
            for (int m = 4; m <= 16; m <<= 1) {
                p0[t] = fmaxf(p0[t], __shfl_xor_sync(0xffffffffu, p0[t], m));
                p1[t] = fmaxf(p1[t], __shfl_xor_sync(0xffffffffu, p1[t], m));
            }
        }
        if (q == 0) {
            #pragma unroll
            for (int t = 0; t < 16; t++) {
                atomicMax(&gsm[t * 8 + 2 * s],     __float_as_int(p0[t]));
                atomicMax(&gsm[t * 8 + 2 * s + 1], __float_as_int(p1[t]));
            }
        }
    }
    __syncthreads();

    // ---- publish partial pooled max; last arriver of the pair finishes the batch ----
    if (tid < 128) d_partial[bidx][tid] = gsm[tid];
    __threadfence();
    __syncthreads();
    if (tid == 0) sIsLast = (atomicAdd(&d_counter[n], 1) == 1);
    __syncthreads();
    if (!sIsLast) return;

    __threadfence();
    if (tid < 128) {
        int comb = max(gsm[tid], d_partial[bidx ^ 1][tid]);
        gsm[tid] = comb;
        __stcs(gout + (size_t)n * Hdim + tid, __int_as_float(comb));
    }
    if (tid == 0) d_counter[n] = 0;   // self-reset for next graph replay
    __syncthreads();

    // broadcast g into out[n, :, H:2H] (whole batch)
    float4 gv;
    gv.x = __int_as_float(gsm[lane * 4 + 0]);
    gv.y = __int_as_float(gsm[lane * 4 + 1]);
    gv.z = __int_as_float(gsm[lane * 4 + 2]);
    gv.w = __int_as_float(gsm[lane * 4 + 3]);
    float* obase = out + (size_t)n * L * (2 * Hdim) + Hdim;
    for (int r = warp; r < L; r += 16)
        __stcs(reinterpret_cast<float4*>(obase + (size_t)r * (2 * Hdim) + lane * 4), gv);
}

extern "C" void kernel_launch(void* const* d_in, const int* in_sizes, int n_in,
                              void* d_out, int out_size) {
    const float* x     = (const float*)d_in[0];
    const int*   mask  = (const int*)d_in[1];
    const float* W     = (const float*)d_in[2];
    const float* bias  = (const float*)d_in[3];
    const float* gamma = (const float*)d_in[4];
    const float* beta  = (const float*)d_in[5];
    float* out = (float*)d_out;

    const int NL = in_sizes[1];
    const long long ysize = (long long)NL * 2 * Hdim;
    const int N = (int)(((long long)out_size - ysize) / Hdim);
    const int L = NL / N;
    float* g = out + ysize;

    fused_kernel<<<2 * N, 512>>>(x, mask, W, bias, gamma, beta, out, g, L);
}

// round 7
// speedup vs baseline: 1.0847x; 1.0847x over previous
#include <cuda_runtime.h>
#include <cuda_fp16.h>
#include <cstdint>

#define LN_EPS 1e-5f

static constexpr int Fdim = 64;
static constexpr int Hdim = 128;

// pack two floats as fp16x2: lo -> low half, hi -> high half
__device__ __forceinline__ uint32_t packh(float lo, float hi) {
    uint32_t r;
    asm("cvt.rn.f16x2.f32 %0, %1, %2;" : "=r"(r) : "f"(hi), "f"(lo));
    return r;
}

__device__ __forceinline__ void mma_f16(float c[4], const uint32_t a[4], const uint32_t b[2]) {
    asm volatile(
        "mma.sync.aligned.m16n8k16.row.col.f32.f16.f16.f32 "
        "{%0,%1,%2,%3}, {%4,%5,%6,%7}, {%8,%9}, {%0,%1,%2,%3};\n"
        : "+f"(c[0]), "+f"(c[1]), "+f"(c[2]), "+f"(c[3])
        : "r"(a[0]), "r"(a[1]), "r"(a[2]), "r"(a[3]), "r"(b[0]), "r"(b[1]));
}

// One CTA per batch n; 16 warps x 16 rows = 256 rows/sweep, L/256 sweeps.
// Single-pass fp16 GEMM -> bias -> LN -> ReLU -> write y; pooled max via smem
// atomics; then g write + broadcast. (R3 structure, 1/3 the tensor MACs.)
extern "C" __global__ void __launch_bounds__(512, 1)
fused_kernel(const float* __restrict__ x, const int* __restrict__ mask,
             const float* __restrict__ W, const float* __restrict__ bias,
             const float* __restrict__ gamma, const float* __restrict__ beta,
             float* __restrict__ out, float* __restrict__ gout, int L)
{
    __shared__ uint2 Bfrag[4 * 16 * 32];   // 16 KB
    __shared__ int   gsm[128];             // pooled max (int bits of floats >= 0)

    const int tid = threadIdx.x;
    const int n   = blockIdx.x;

    // pack W into fp16 mma B-fragment order
    for (int idx = tid; idx < 4 * 16 * 32; idx += 512) {
        int lane = idx & 31;
        int t    = (idx >> 5) & 15;
        int ks   = idx >> 9;
        int q = lane >> 2, s = lane & 3;
        int h  = t * 8 + q;
        int f0 = ks * 16 + s * 2;
        float2 w01 = *reinterpret_cast<const float2*>(W + h * Fdim + f0);
        float2 w89 = *reinterpret_cast<const float2*>(W + h * Fdim + f0 + 8);
        uint2 v;
        v.x = packh(w01.x, w01.y);
        v.y = packh(w89.x, w89.y);
        Bfrag[idx] = v;
    }
    if (tid < 128) gsm[tid] = 0;
    __syncthreads();

    const int lane = tid & 31;
    const int warp = tid >> 5;
    const int q = lane >> 2, s = lane & 3;

    for (int rb = warp * 16; rb < L; rb += 256) {
        const size_t rowA = (size_t)n * L + rb + q;
        const size_t rowB = rowA + 8;
        const float* xA = x + rowA * Fdim;
        const float* xB = x + rowB * Fdim;

        float acc[16][4];
        #pragma unroll
        for (int t = 0; t < 16; t++)
            acc[t][0] = acc[t][1] = acc[t][2] = acc[t][3] = 0.f;

        #pragma unroll
        for (int ks = 0; ks < 4; ks++) {
            const int f0 = ks * 16 + s * 2;
            float2 A0 = *reinterpret_cast<const float2*>(xA + f0);
            float2 A8 = *reinterpret_cast<const float2*>(xA + f0 + 8);
            float2 B0 = *reinterpret_cast<const float2*>(xB + f0);
            float2 B8 = *reinterpret_cast<const float2*>(xB + f0 + 8);
            uint32_t ah[4] = { packh(A0.x, A0.y), packh(B0.x, B0.y),
                               packh(A8.x, A8.y), packh(B8.x, B8.y) };
            const uint2* Bp = Bfrag + ks * 512 + lane;
            #pragma unroll
            for (int t = 0; t < 16; t++) {
                uint2 bv = Bp[t * 32];
                uint32_t bh[2] = { bv.x, bv.y };
                mma_f16(acc[t], ah, bh);
            }
        }

        #pragma unroll
        for (int t = 0; t < 16; t++) {
            float2 bb = *reinterpret_cast<const float2*>(bias + t * 8 + 2 * s);
            acc[t][0] += bb.x; acc[t][1] += bb.y;
            acc[t][2] += bb.x; acc[t][3] += bb.y;
        }

        float sumA = 0.f, sqA = 0.f, sumB = 0.f, sqB = 0.f;
        #pragma unroll
        for (int t = 0; t < 16; t++) {
            sumA += acc[t][0] + acc[t][1];
            sqA  += acc[t][0] * acc[t][0] + acc[t][1] * acc[t][1];
            sumB += acc[t][2] + acc[t][3];
            sqB  += acc[t][2] * acc[t][2] + acc[t][3] * acc[t][3];
        }
        #pragma unroll
        for (int m = 1; m <= 2; m <<= 1) {
            sumA += __shfl_xor_sync(0xffffffffu, sumA, m);
            sqA  += __shfl_xor_sync(0xffffffffu, sqA, m);
            sumB += __shfl_xor_sync(0xffffffffu, sumB, m);
            sqB  += __shfl_xor_sync(0xffffffffu, sqB, m);
        }
        const float inv = 1.0f / (float)Hdim;
        float muA = sumA * inv, muB = sumB * inv;
        float rsA = rsqrtf(fmaxf(sqA * inv - muA * muA, 0.f) + LN_EPS);
        float rsB = rsqrtf(fmaxf(sqB * inv - muB * muB, 0.f) + LN_EPS);

        const bool mA = (mask[rowA] != 0);
        const bool mB = (mask[rowB] != 0);
        float* outA = out + rowA * (2 * Hdim);
        float* outB = out + rowB * (2 * Hdim);

        float p0[16], p1[16];
        #pragma unroll
        for (int t = 0; t < 16; t++) {
            int col = t * 8 + 2 * s;
            float2 gg = *reinterpret_cast<const float2*>(gamma + col);
            float2 bt = *reinterpret_cast<const float2*>(beta + col);
            float yA0 = fmaxf((acc[t][0] - muA) * rsA * gg.x + bt.x, 0.f);
            float yA1 = fmaxf((acc[t][1] - muA) * rsA * gg.y + bt.y, 0.f);
            float yB0 = fmaxf((acc[t][2] - muB) * rsB * gg.x + bt.x, 0.f);
            float yB1 = fmaxf((acc[t][3] - muB) * rsB * gg.y + bt.y, 0.f);
            *reinterpret_cast<float2*>(outA + col) = make_float2(yA0, yA1);
            *reinterpret_cast<float2*>(outB + col) = make_float2(yB0, yB1);
            p0[t] = fmaxf(mA ? yA0 : 0.f, mB ? yB0 : 0.f);
            p1[t] = fmaxf(mA ? yA1 : 0.f, mB ? yB1 : 0.f);
        }

        #pragma unroll
        for (int t = 0; t < 16; t++) {
            #pragma unroll
            for (int m = 4; m <= 16; m <<= 1) {
                p0[t] = fmaxf(p0[t], __shfl_xor_sync(0xffffffffu, p0[t], m));
                p1[t] = fmaxf(p1[t], __shfl_xor_sync(0xffffffffu, p1[t], m));
            }
        }
        if (q == 0) {
            #pragma unroll
            for (int t = 0; t < 16; t++) {
                atomicMax(&gsm[t * 8 + 2 * s],     __float_as_int(p0[t]));
                atomicMax(&gsm[t * 8 + 2 * s + 1], __float_as_int(p1[t]));
            }
        }
    }
    __syncthreads();

    if (tid < 128)
        gout[(size_t)n * Hdim + tid] = __int_as_float(gsm[tid]);

    // broadcast g into out[n, :, H:2H] — 16 warps x float4 lanes
    float4 gv;
    gv.x = __int_as_float(gsm[lane * 4 + 0]);
    gv.y = __int_as_float(gsm[lane * 4 + 1]);
    gv.z = __int_as_float(gsm[lane * 4 + 2]);
    gv.w = __int_as_float(gsm[lane * 4 + 3]);
    float* obase = out + (size_t)n * L * (2 * Hdim) + Hdim;
    for (int r = warp; r < L; r += 16)
        *reinterpret_cast<float4*>(obase + (size_t)r * (2 * Hdim) + lane * 4) = gv;
}

extern "C" void kernel_launch(void* const* d_in, const int* in_sizes, int n_in,
                              void* d_out, int out_size) {
    const float* x     = (const float*)d_in[0];
    const int*   mask  = (const int*)d_in[1];
    const float* W     = (const float*)d_in[2];
    const float* bias  = (const float*)d_in[3];
    const float* gamma = (const float*)d_in[4];
    const float* beta  = (const float*)d_in[5];
    float* out = (float*)d_out;

    const int NL = in_sizes[1];
    const long long ysize = (long long)NL * 2 * Hdim;
    const int N = (int)(((long long)out_size - ysize) / Hdim);
    const int L = NL / N;
    float* g = out + ysize;

    fused_kernel<<<N, 512>>>(x, mask, W, bias, gamma, beta, out, g, L);
}